// round 13
// baseline (speedup 1.0000x reference)
#include <cuda_runtime.h>
#include <cuda_fp16.h>
#include <cstdint>

#define DIM    2048
#define NROWS  16384   // 4 * 4096

// GEMM tiling (single fp16 pass, K = 2048) — 3 CTA/SM config
#define BM 128
#define BN 64
#define BK 64
#define NKT 32
#define GTHREADS 256               // 8 warps, 4x2 warp grid, warp tile 32x32
#define ABYTES (BM * BK * 2)       // 16384
#define BBYTES (BN * BK * 2)       // 8192
#define STAGE  (ABYTES + BBYTES)   // 24576
#define NSTAGE 3
#define GEMM_SMEM (NSTAGE * STAGE) // 73728  -> 3 CTAs/SM (221KB)

#define WPARTS 2048

// ---------------------------------------------------------------------------
// Scratch (static __device__ globals — allocation-free per harness rules)
// ---------------------------------------------------------------------------
__device__ float   g_wpart[WPARTS];
__device__ float   g_wscale;
__device__ float   g_B1[DIM * DIM];            // fwht_rows(ternary(W))   [o][d]
__device__ float   g_B1T[DIM * DIM];           // transpose               [d][o]
__device__ __half  g_BqT[DIM * DIM];           // fwht rows of B1T (fp16) [d][o]
__device__ __half  g_Bq[DIM * DIM];            // final B operand         [o][d]
__device__ __half  g_Xq[(size_t)NROWS * DIM];  // x_int exact in fp16
__device__ float   g_rowscale[NROWS];          // x_scale / 7

// ---------------------------------------------------------------------------
// Helpers
// ---------------------------------------------------------------------------
static __device__ __forceinline__ uint32_t smem_u32(const void* p) {
    uint32_t a;
    asm("{ .reg .u64 t; cvta.to.shared.u64 t, %1; cvt.u32.u64 %0, t; }"
        : "=r"(a) : "l"(p));
    return a;
}

static __device__ __forceinline__ void cp_async16(uint32_t dst, const void* src) {
    asm volatile("cp.async.cg.shared.global [%0], [%1], 16;" :: "r"(dst), "l"(src));
}

static __device__ __forceinline__ void ldmatrix_x4(uint32_t* r, uint32_t addr) {
    asm volatile("ldmatrix.sync.aligned.m8n8.x4.shared.b16 {%0,%1,%2,%3}, [%4];"
                 : "=r"(r[0]), "=r"(r[1]), "=r"(r[2]), "=r"(r[3]) : "r"(addr));
}

static __device__ __forceinline__ void ldmatrix_x2(uint32_t* r, uint32_t addr) {
    asm volatile("ldmatrix.sync.aligned.m8n8.x2.shared.b16 {%0,%1}, [%2];"
                 : "=r"(r[0]), "=r"(r[1]) : "r"(addr));
}

static __device__ __forceinline__ void mma_f16(float* c, const uint32_t* a, const uint32_t* b) {
    asm volatile(
        "mma.sync.aligned.m16n8k16.row.col.f32.f16.f16.f32 "
        "{%0,%1,%2,%3}, {%4,%5,%6,%7}, {%8,%9}, {%0,%1,%2,%3};"
        : "+f"(c[0]), "+f"(c[1]), "+f"(c[2]), "+f"(c[3])
        : "r"(a[0]), "r"(a[1]), "r"(a[2]), "r"(a[3]), "r"(b[0]), "r"(b[1]));
}

// ---------------------------------------------------------------------------
// Block reductions (deterministic fixed-order trees)
// ---------------------------------------------------------------------------
static __device__ __forceinline__ float block_sum256(float v, float* red) {
    #pragma unroll
    for (int o = 16; o; o >>= 1) v += __shfl_xor_sync(0xFFFFFFFFu, v, o);
    if ((threadIdx.x & 31) == 0) red[threadIdx.x >> 5] = v;
    __syncthreads();
    float t = red[0];
    #pragma unroll
    for (int w = 1; w < 8; w++) t += red[w];
    __syncthreads();
    return t;
}

static __device__ __forceinline__ float block_max256(float v, float* red) {
    #pragma unroll
    for (int o = 16; o; o >>= 1) v = fmaxf(v, __shfl_xor_sync(0xFFFFFFFFu, v, o));
    if ((threadIdx.x & 31) == 0) red[threadIdx.x >> 5] = v;
    __syncthreads();
    float t = red[0];
    #pragma unroll
    for (int w = 1; w < 8; w++) t = fmaxf(t, red[w]);
    __syncthreads();
    return t;
}

// ---------------------------------------------------------------------------
// K0: mean(|W|) -> g_wscale  (2048 partials for memory-level parallelism)
// ---------------------------------------------------------------------------
__global__ void k_wabs_part(const float* __restrict__ W) {
    float s = 0.f;
    #pragma unroll
    for (int i = 0; i < (DIM * DIM) / (WPARTS * 256); i++)
        s += fabsf(W[blockIdx.x * 256 + threadIdx.x + i * WPARTS * 256]);
    #pragma unroll
    for (int o = 16; o; o >>= 1) s += __shfl_xor_sync(0xFFFFFFFFu, s, o);
    __shared__ float red[8];
    if ((threadIdx.x & 31) == 0) red[threadIdx.x >> 5] = s;
    __syncthreads();
    if (threadIdx.x == 0) {
        float t = 0.f;
        #pragma unroll
        for (int w = 0; w < 8; w++) t += red[w];
        g_wpart[blockIdx.x] = t;
    }
}

__global__ void k_wabs_fin() {
    float s = 0.f;
    #pragma unroll
    for (int j = 0; j < WPARTS / 256; j++)
        s += g_wpart[threadIdx.x * (WPARTS / 256) + j];
    #pragma unroll
    for (int o = 16; o; o >>= 1) s += __shfl_xor_sync(0xFFFFFFFFu, s, o);
    __shared__ float red[8];
    if ((threadIdx.x & 31) == 0) red[threadIdx.x >> 5] = s;
    __syncthreads();
    if (threadIdx.x == 0) {
        float t = 0.f;
        #pragma unroll
        for (int w = 0; w < 8; w++) t += red[w];
        g_wscale = fmaxf(t / (float)(DIM * DIM), 1e-6f);
    }
}

// ---------------------------------------------------------------------------
// Register/shuffle FWHT over one 2048-row, 256 threads x 8 elements.
// ---------------------------------------------------------------------------
#define BFLY(a, b) { float _x = (a), _y = (b); (a) = _x + _y; (b) = _x - _y; }

static __device__ __forceinline__ void fwht_reg8(float* v) {
    BFLY(v[0], v[1]); BFLY(v[2], v[3]); BFLY(v[4], v[5]); BFLY(v[6], v[7]);
    BFLY(v[0], v[2]); BFLY(v[1], v[3]); BFLY(v[4], v[6]); BFLY(v[5], v[7]);
    BFLY(v[0], v[4]); BFLY(v[1], v[5]); BFLY(v[2], v[6]); BFLY(v[3], v[7]);
}

static __device__ __forceinline__ void fwht_shfl5(float* v, int lane) {
    #pragma unroll
    for (int b = 1; b <= 16; b <<= 1) {
        #pragma unroll
        for (int j = 0; j < 8; j++) {
            float p = __shfl_xor_sync(0xFFFFFFFFu, v[j], b);
            v[j] = (lane & b) ? (p - v[j]) : (v[j] + p);
        }
    }
}

// K1: ternarize row o of W, FWHT, write g_B1[o][d]
__global__ void __launch_bounds__(256)
k_wq_fwht(const float* __restrict__ W) {
    __shared__ float s[DIM];
    const int o = blockIdx.x, t = threadIdx.x, lane = t & 31, w = t >> 5;
    const float ws = g_wscale, th = 0.5f * ws;
    const float* wr = W + (size_t)o * DIM;
    float v[8];
    #pragma unroll
    for (int j = 0; j < 8; j++) {
        float x = wr[j * 256 + t];
        v[j] = (x > th) ? ws : ((x < -th) ? -ws : 0.f);
    }
    fwht_reg8(v);            // bits 8,9,10
    fwht_shfl5(v, lane);     // bits 0..4
    #pragma unroll
    for (int j = 0; j < 8; j++) s[j * 256 + t] = v[j];
    __syncthreads();
    #pragma unroll
    for (int j = 0; j < 8; j++) v[j] = s[w * 256 + j * 32 + lane];
    fwht_reg8(v);            // bits 5,6,7
    float* orow = g_B1 + (size_t)o * DIM;
    #pragma unroll
    for (int j = 0; j < 8; j++) orow[w * 256 + j * 32 + lane] = v[j];
}

// K2b: FWHT rows of g_B1T (FWHT over o), round to fp16, write g_BqT[d][o]
__global__ void __launch_bounds__(256)
k_fwht_rows_half() {
    __shared__ float s[DIM];
    const int d = blockIdx.x, t = threadIdx.x, lane = t & 31, w = t >> 5;
    const float* ir = g_B1T + (size_t)d * DIM;
    float v[8];
    #pragma unroll
    for (int j = 0; j < 8; j++) v[j] = ir[j * 256 + t];
    fwht_reg8(v);
    fwht_shfl5(v, lane);
    #pragma unroll
    for (int j = 0; j < 8; j++) s[j * 256 + t] = v[j];
    __syncthreads();
    #pragma unroll
    for (int j = 0; j < 8; j++) v[j] = s[w * 256 + j * 32 + lane];
    fwht_reg8(v);
    __half* orow = g_BqT + (size_t)d * DIM;
    #pragma unroll
    for (int j = 0; j < 8; j++)
        orow[w * 256 + j * 32 + lane] = __float2half_rn(v[j]);
}

// K2a: f32 tiled transpose g_B1 -> g_B1T
__global__ void __launch_bounds__(256)
k_tr32() {
    __shared__ float t[32][33];
    const int tx = threadIdx.x, ty = threadIdx.y;
    const int x = blockIdx.x * 32 + tx, y0 = blockIdx.y * 32 + ty;
    #pragma unroll
    for (int j = 0; j < 4; j++)
        t[ty + j * 8][tx] = g_B1[(size_t)(y0 + j * 8) * DIM + x];
    __syncthreads();
    const int x2 = blockIdx.y * 32 + tx, y2 = blockIdx.x * 32 + ty;
    #pragma unroll
    for (int j = 0; j < 4; j++)
        g_B1T[(size_t)(y2 + j * 8) * DIM + x2] = t[tx][ty + j * 8];
}

// K2c: f16 tiled transpose g_BqT -> g_Bq
__global__ void __launch_bounds__(256)
k_tr16() {
    __shared__ __half t[32][34];
    const int tx = threadIdx.x, ty = threadIdx.y;
    const int x = blockIdx.x * 32 + tx, y0 = blockIdx.y * 32 + ty;
    #pragma unroll
    for (int j = 0; j < 4; j++)
        t[ty + j * 8][tx] = g_BqT[(size_t)(y0 + j * 8) * DIM + x];
    __syncthreads();
    const int x2 = blockIdx.y * 32 + tx, y2 = blockIdx.x * 32 + ty;
    #pragma unroll
    for (int j = 0; j < 4; j++)
        g_Bq[(size_t)(y2 + j * 8) * DIM + x2] = t[tx][ty + j * 8];
}

// ---------------------------------------------------------------------------
// K3: LayerNorm + 4-bit symmetric quant per row (x_int exact in fp16).
// ---------------------------------------------------------------------------
__global__ void k_ln_quant(const float* __restrict__ x,
                           const float* __restrict__ gamma,
                           const float* __restrict__ beta) {
    __shared__ float red[8];
    const int row = blockIdx.x;
    const float* xr = x + (size_t)row * DIM;
    float v[8];
    float s = 0.f;
    #pragma unroll
    for (int t = 0; t < 8; t++) { v[t] = xr[threadIdx.x + t * 256]; s += v[t]; }
    s = block_sum256(s, red);
    const float mu = s * (1.f / (float)DIM);
    float sq = 0.f;
    #pragma unroll
    for (int t = 0; t < 8; t++) { float c = v[t] - mu; sq += c * c; }
    sq = block_sum256(sq, red);
    const float rstd = rsqrtf(sq * (1.f / (float)DIM) + 1e-5f);
    float mx = 0.f;
    #pragma unroll
    for (int t = 0; t < 8; t++) {
        int j = threadIdx.x + t * 256;
        float xl = (v[t] - mu) * rstd * gamma[j] + beta[j];
        v[t] = xl;
        mx = fmaxf(mx, fabsf(xl));
    }
    mx = block_max256(mx, red);
    const float xs = fmaxf(mx, 1e-6f);
    #pragma unroll
    for (int t = 0; t < 8; t++) {
        float r = rintf(v[t] * 7.0f / xs);   // round-half-even matches jnp.round
        r = fminf(fmaxf(r, -7.f), 7.f);
        g_Xq[(size_t)row * DIM + threadIdx.x + t * 256] = __float2half_rn(r);
    }
    if (threadIdx.x == 0) g_rowscale[row] = xs * (1.f / 7.f);
}

// ---------------------------------------------------------------------------
// K4: GEMM via mma.sync (HMMA fp16, fp32 accum), 3 CTAs/SM.
//   CTA 128x64, BK=64, 256 threads, 8 warps in 4x2 grid, warp tile 32x32.
//   3-stage cp.async ring + supertile rasterization.
// ---------------------------------------------------------------------------
static __device__ __forceinline__ void load_A(uint32_t base, const __half* gA,
                                              int ksrc, int tid) {
    #pragma unroll
    for (int i = 0; i < 4; i++) {
        int idx = tid + i * GTHREADS;
        int r = idx >> 3, c = idx & 7;
        uint32_t so = (uint32_t)(r * 128 + ((c ^ (r & 7)) << 4));
        cp_async16(base + so, (const char*)(gA + (size_t)r * DIM + ksrc) + c * 16);
    }
}

static __device__ __forceinline__ void load_B(uint32_t base, const __half* gB,
                                              int ksrc, int tid) {
    #pragma unroll
    for (int i = 0; i < 2; i++) {
        int idx = tid + i * GTHREADS;
        int r = idx >> 3, c = idx & 7;
        uint32_t so = (uint32_t)(r * 128 + ((c ^ (r & 7)) << 4));
        cp_async16(base + so, (const char*)(gB + (size_t)r * DIM + ksrc) + c * 16);
    }
}

__global__ void __launch_bounds__(GTHREADS, 3)
k_gemm(float* __restrict__ out) {
    extern __shared__ char smem[];
    const uint32_t sb = smem_u32(smem);
    const int tid  = threadIdx.x;
    const int lane = tid & 31;
    const int wid  = tid >> 5;            // 0..7
    const int wm   = (wid >> 1) * 32;     // warp m-offset (4 rows of warps)
    const int wn   = (wid & 1) * 32;      // warp n-offset (2 cols of warps)

    // Supertile rasterization: 16 mt x 32 nt = 512-CTA supertiles.
    // Working set per group: A 8MB + B 8MB -> L2-resident.
    const int bid = blockIdx.x;           // 0..4095 (128 mt x 32 nt)
    const int st  = bid >> 9;             // 8 supertiles
    const int r9  = bid & 511;
    const int mt  = st * 16 + (r9 & 15);
    const int nt  = r9 >> 4;
    const int mBase = mt * BM;
    const int nBase = nt * BN;

    const __half* gA = g_Xq + (size_t)mBase * DIM;
    const __half* gB = g_Bq + (size_t)nBase * DIM;

    float acc[2][4][4];
    #pragma unroll
    for (int i = 0; i < 2; i++)
        #pragma unroll
        for (int j = 0; j < 4; j++)
            #pragma unroll
            for (int q = 0; q < 4; q++) acc[i][j][q] = 0.f;

    // Prologue: stages 0,1 <- kt 0,1
    #pragma unroll
    for (int p = 0; p < NSTAGE - 1; p++) {
        load_A(sb + p * STAGE, gA, p * BK, tid);
        load_B(sb + p * STAGE + ABYTES, gB, p * BK, tid);
        asm volatile("cp.async.commit_group;" ::: "memory");
    }

    int stage = 0;
    for (int kt = 0; kt < NKT; kt++) {
        if (kt < NKT - 1) asm volatile("cp.async.wait_group 1;" ::: "memory");
        else              asm volatile("cp.async.wait_group 0;" ::: "memory");
        __syncthreads();

        const uint32_t aB = sb + stage * STAGE;
        const uint32_t bB = aB + ABYTES;

        #pragma unroll
        for (int ks = 0; ks < 4; ks++) {
            uint32_t af[2][4], bf[4][2];
            #pragma unroll
            for (int im = 0; im < 2; im++) {
                int r = wm + im * 16 + (lane & 15);
                uint32_t chunk = (uint32_t)((ks * 2 + (lane >> 4)) ^ (r & 7));
                ldmatrix_x4(af[im], aB + r * 128 + (chunk << 4));
            }
            #pragma unroll
            for (int in = 0; in < 4; in++) {
                int r = wn + in * 8 + (lane & 7);
                uint32_t chunk = (uint32_t)((ks * 2 + ((lane >> 3) & 1)) ^ (r & 7));
                ldmatrix_x2(bf[in], bB + r * 128 + (chunk << 4));
            }
            #pragma unroll
            for (int im = 0; im < 2; im++)
                #pragma unroll
                for (int in = 0; in < 4; in++)
                    mma_f16(acc[im][in], af[im], bf[in]);
        }

        if (kt + NSTAGE - 1 < NKT) {
            const int k2 = kt + NSTAGE - 1;
            int st2 = stage + NSTAGE - 1;
            if (st2 >= NSTAGE) st2 -= NSTAGE;
            const uint32_t nb = sb + st2 * STAGE;
            load_A(nb, gA, k2 * BK, tid);
            load_B(nb + ABYTES, gB, k2 * BK, tid);
            asm volatile("cp.async.commit_group;" ::: "memory");
        }
        stage = (stage + 1 == NSTAGE) ? 0 : stage + 1;
    }

    // Epilogue: d frag -> (row = lane/4 [+8], col = 2*(lane%4) [+1])
    #pragma unroll
    for (int im = 0; im < 2; im++) {
        const int r0 = mBase + wm + im * 16 + (lane >> 2);
        const int r1 = r0 + 8;
        const float s0 = g_rowscale[r0];
        const float s1 = g_rowscale[r1];
        #pragma unroll
        for (int in = 0; in < 4; in++) {
            const int col = nBase + wn + in * 8 + (lane & 3) * 2;
            float2 v0 = make_float2(acc[im][in][0] * s0, acc[im][in][1] * s0);
            float2 v1 = make_float2(acc[im][in][2] * s1, acc[im][in][3] * s1);
            *reinterpret_cast<float2*>(out + (size_t)r0 * DIM + col) = v0;
            *reinterpret_cast<float2*>(out + (size_t)r1 * DIM + col) = v1;
        }
    }
}

// ---------------------------------------------------------------------------
// Launcher
// ---------------------------------------------------------------------------
extern "C" void kernel_launch(void* const* d_in, const int* in_sizes, int n_in,
                              void* d_out, int out_size) {
    const float* x     = (const float*)d_in[0];
    const float* W     = (const float*)d_in[1];
    const float* gamma = (const float*)d_in[2];
    const float* beta  = (const float*)d_in[3];
    float* out = (float*)d_out;

    cudaFuncSetAttribute(k_gemm, cudaFuncAttributeMaxDynamicSharedMemorySize,
                         GEMM_SMEM);

    k_wabs_part<<<WPARTS, 256>>>(W);
    k_wabs_fin<<<1, 256>>>();
    k_wq_fwht<<<DIM, 256>>>(W);
    {
        dim3 tb(32, 8);
        dim3 tg(DIM / 32, DIM / 32);
        k_tr32<<<tg, tb>>>();
    }
    k_fwht_rows_half<<<DIM, 256>>>();
    {
        dim3 tb(32, 8);
        dim3 tg(DIM / 32, DIM / 32);
        k_tr16<<<tg, tb>>>();
    }
    k_ln_quant<<<NROWS, 256>>>(x, gamma, beta);

    k_gemm<<<(NROWS / BM) * (DIM / BN), GTHREADS, GEMM_SMEM>>>(out);
}

// round 14
// speedup vs baseline: 1.0412x; 1.0412x over previous
#include <cuda_runtime.h>
#include <cuda_fp16.h>
#include <cstdint>

#define DIM    2048
#define NROWS  16384   // 4 * 4096

// GEMM tiling (single fp16 pass, K = 2048) — R12-proven 2 CTA/SM config
#define BM 128
#define BN 128
#define BK 64
#define NKT 32
#define GTHREADS 256               // 8 warps, 2x4 warp grid, warp tile 64x32
#define ABYTES (BM * BK * 2)       // 16384
#define BBYTES (BN * BK * 2)       // 16384
#define STAGE  (ABYTES + BBYTES)   // 32768
#define NSTAGE 3
#define GEMM_SMEM (NSTAGE * STAGE) // 98304  -> 2 CTAs/SM

#define WPARTS 2048

// ---------------------------------------------------------------------------
// Scratch (static __device__ globals — allocation-free per harness rules)
// ---------------------------------------------------------------------------
__device__ float   g_wpart[WPARTS];
__device__ float   g_wscale;
__device__ float   g_B1[DIM * DIM];            // fwht_rows(ternary(W))   [o][d]
__device__ float   g_B1T[DIM * DIM];           // transpose               [d][o]
__device__ __half  g_BqT[DIM * DIM];           // fwht rows of B1T (fp16) [d][o]
__device__ __half  g_Bq[DIM * DIM];            // final B operand         [o][d]
__device__ __half  g_Xq[(size_t)NROWS * DIM];  // x_int exact in fp16
__device__ float   g_rowscale[NROWS];          // x_scale / 7

// ---------------------------------------------------------------------------
// Helpers
// ---------------------------------------------------------------------------
static __device__ __forceinline__ uint32_t smem_u32(const void* p) {
    uint32_t a;
    asm("{ .reg .u64 t; cvta.to.shared.u64 t, %1; cvt.u32.u64 %0, t; }"
        : "=r"(a) : "l"(p));
    return a;
}

static __device__ __forceinline__ void cp_async16(uint32_t dst, const void* src) {
    asm volatile("cp.async.cg.shared.global [%0], [%1], 16;" :: "r"(dst), "l"(src));
}

static __device__ __forceinline__ void ldmatrix_x4(uint32_t* r, uint32_t addr) {
    asm volatile("ldmatrix.sync.aligned.m8n8.x4.shared.b16 {%0,%1,%2,%3}, [%4];"
                 : "=r"(r[0]), "=r"(r[1]), "=r"(r[2]), "=r"(r[3]) : "r"(addr));
}

static __device__ __forceinline__ void ldmatrix_x2(uint32_t* r, uint32_t addr) {
    asm volatile("ldmatrix.sync.aligned.m8n8.x2.shared.b16 {%0,%1}, [%2];"
                 : "=r"(r[0]), "=r"(r[1]) : "r"(addr));
}

static __device__ __forceinline__ void mma_f16(float* c, const uint32_t* a, const uint32_t* b) {
    asm volatile(
        "mma.sync.aligned.m16n8k16.row.col.f32.f16.f16.f32 "
        "{%0,%1,%2,%3}, {%4,%5,%6,%7}, {%8,%9}, {%0,%1,%2,%3};"
        : "+f"(c[0]), "+f"(c[1]), "+f"(c[2]), "+f"(c[3])
        : "r"(a[0]), "r"(a[1]), "r"(a[2]), "r"(a[3]), "r"(b[0]), "r"(b[1]));
}

// ---------------------------------------------------------------------------
// Block reductions (deterministic fixed-order trees)
// ---------------------------------------------------------------------------
static __device__ __forceinline__ float block_sum256(float v, float* red) {
    #pragma unroll
    for (int o = 16; o; o >>= 1) v += __shfl_xor_sync(0xFFFFFFFFu, v, o);
    if ((threadIdx.x & 31) == 0) red[threadIdx.x >> 5] = v;
    __syncthreads();
    float t = red[0];
    #pragma unroll
    for (int w = 1; w < 8; w++) t += red[w];
    __syncthreads();
    return t;
}

static __device__ __forceinline__ float block_max256(float v, float* red) {
    #pragma unroll
    for (int o = 16; o; o >>= 1) v = fmaxf(v, __shfl_xor_sync(0xFFFFFFFFu, v, o));
    if ((threadIdx.x & 31) == 0) red[threadIdx.x >> 5] = v;
    __syncthreads();
    float t = red[0];
    #pragma unroll
    for (int w = 1; w < 8; w++) t = fmaxf(t, red[w]);
    __syncthreads();
    return t;
}

// ---------------------------------------------------------------------------
// K0: mean(|W|) -> g_wscale  (2048 partials for memory-level parallelism)
// ---------------------------------------------------------------------------
__global__ void k_wabs_part(const float* __restrict__ W) {
    float s = 0.f;
    #pragma unroll
    for (int i = 0; i < (DIM * DIM) / (WPARTS * 256); i++)
        s += fabsf(W[blockIdx.x * 256 + threadIdx.x + i * WPARTS * 256]);
    #pragma unroll
    for (int o = 16; o; o >>= 1) s += __shfl_xor_sync(0xFFFFFFFFu, s, o);
    __shared__ float red[8];
    if ((threadIdx.x & 31) == 0) red[threadIdx.x >> 5] = s;
    __syncthreads();
    if (threadIdx.x == 0) {
        float t = 0.f;
        #pragma unroll
        for (int w = 0; w < 8; w++) t += red[w];
        g_wpart[blockIdx.x] = t;
    }
}

__global__ void k_wabs_fin() {
    float s = 0.f;
    #pragma unroll
    for (int j = 0; j < WPARTS / 256; j++)
        s += g_wpart[threadIdx.x * (WPARTS / 256) + j];
    #pragma unroll
    for (int o = 16; o; o >>= 1) s += __shfl_xor_sync(0xFFFFFFFFu, s, o);
    __shared__ float red[8];
    if ((threadIdx.x & 31) == 0) red[threadIdx.x >> 5] = s;
    __syncthreads();
    if (threadIdx.x == 0) {
        float t = 0.f;
        #pragma unroll
        for (int w = 0; w < 8; w++) t += red[w];
        g_wscale = fmaxf(t / (float)(DIM * DIM), 1e-6f);
    }
}

// ---------------------------------------------------------------------------
// Register/shuffle FWHT over one 2048-row, 256 threads x 8 elements.
// ---------------------------------------------------------------------------
#define BFLY(a, b) { float _x = (a), _y = (b); (a) = _x + _y; (b) = _x - _y; }

static __device__ __forceinline__ void fwht_reg8(float* v) {
    BFLY(v[0], v[1]); BFLY(v[2], v[3]); BFLY(v[4], v[5]); BFLY(v[6], v[7]);
    BFLY(v[0], v[2]); BFLY(v[1], v[3]); BFLY(v[4], v[6]); BFLY(v[5], v[7]);
    BFLY(v[0], v[4]); BFLY(v[1], v[5]); BFLY(v[2], v[6]); BFLY(v[3], v[7]);
}

static __device__ __forceinline__ void fwht_shfl5(float* v, int lane) {
    #pragma unroll
    for (int b = 1; b <= 16; b <<= 1) {
        #pragma unroll
        for (int j = 0; j < 8; j++) {
            float p = __shfl_xor_sync(0xFFFFFFFFu, v[j], b);
            v[j] = (lane & b) ? (p - v[j]) : (v[j] + p);
        }
    }
}

// K1: ternarize row o of W, FWHT, write g_B1[o][d]
__global__ void __launch_bounds__(256)
k_wq_fwht(const float* __restrict__ W) {
    __shared__ float s[DIM];
    const int o = blockIdx.x, t = threadIdx.x, lane = t & 31, w = t >> 5;
    const float ws = g_wscale, th = 0.5f * ws;
    const float* wr = W + (size_t)o * DIM;
    float v[8];
    #pragma unroll
    for (int j = 0; j < 8; j++) {
        float x = wr[j * 256 + t];
        v[j] = (x > th) ? ws : ((x < -th) ? -ws : 0.f);
    }
    fwht_reg8(v);            // bits 8,9,10
    fwht_shfl5(v, lane);     // bits 0..4
    #pragma unroll
    for (int j = 0; j < 8; j++) s[j * 256 + t] = v[j];
    __syncthreads();
    #pragma unroll
    for (int j = 0; j < 8; j++) v[j] = s[w * 256 + j * 32 + lane];
    fwht_reg8(v);            // bits 5,6,7
    float* orow = g_B1 + (size_t)o * DIM;
    #pragma unroll
    for (int j = 0; j < 8; j++) orow[w * 256 + j * 32 + lane] = v[j];
}

// K2b: FWHT rows of g_B1T (FWHT over o), round to fp16, write g_BqT[d][o]
__global__ void __launch_bounds__(256)
k_fwht_rows_half() {
    __shared__ float s[DIM];
    const int d = blockIdx.x, t = threadIdx.x, lane = t & 31, w = t >> 5;
    const float* ir = g_B1T + (size_t)d * DIM;
    float v[8];
    #pragma unroll
    for (int j = 0; j < 8; j++) v[j] = ir[j * 256 + t];
    fwht_reg8(v);
    fwht_shfl5(v, lane);
    #pragma unroll
    for (int j = 0; j < 8; j++) s[j * 256 + t] = v[j];
    __syncthreads();
    #pragma unroll
    for (int j = 0; j < 8; j++) v[j] = s[w * 256 + j * 32 + lane];
    fwht_reg8(v);
    __half* orow = g_BqT + (size_t)d * DIM;
    #pragma unroll
    for (int j = 0; j < 8; j++)
        orow[w * 256 + j * 32 + lane] = __float2half_rn(v[j]);
}

// K2a: f32 tiled transpose g_B1 -> g_B1T
__global__ void __launch_bounds__(256)
k_tr32() {
    __shared__ float t[32][33];
    const int tx = threadIdx.x, ty = threadIdx.y;
    const int x = blockIdx.x * 32 + tx, y0 = blockIdx.y * 32 + ty;
    #pragma unroll
    for (int j = 0; j < 4; j++)
        t[ty + j * 8][tx] = g_B1[(size_t)(y0 + j * 8) * DIM + x];
    __syncthreads();
    const int x2 = blockIdx.y * 32 + tx, y2 = blockIdx.x * 32 + ty;
    #pragma unroll
    for (int j = 0; j < 4; j++)
        g_B1T[(size_t)(y2 + j * 8) * DIM + x2] = t[tx][ty + j * 8];
}

// K2c: f16 tiled transpose g_BqT -> g_Bq
__global__ void __launch_bounds__(256)
k_tr16() {
    __shared__ __half t[32][34];
    const int tx = threadIdx.x, ty = threadIdx.y;
    const int x = blockIdx.x * 32 + tx, y0 = blockIdx.y * 32 + ty;
    #pragma unroll
    for (int j = 0; j < 4; j++)
        t[ty + j * 8][tx] = g_BqT[(size_t)(y0 + j * 8) * DIM + x];
    __syncthreads();
    const int x2 = blockIdx.y * 32 + tx, y2 = blockIdx.x * 32 + ty;
    #pragma unroll
    for (int j = 0; j < 4; j++)
        g_Bq[(size_t)(y2 + j * 8) * DIM + x2] = t[tx][ty + j * 8];
}

// ---------------------------------------------------------------------------
// K3: LayerNorm + 4-bit symmetric quant per row (x_int exact in fp16).
//     Vectorized float4 I/O: each thread owns elements [8t, 8t+4) pairs.
// ---------------------------------------------------------------------------
__global__ void __launch_bounds__(256)
k_ln_quant(const float* __restrict__ x,
           const float* __restrict__ gamma,
           const float* __restrict__ beta) {
    __shared__ float red[8];
    const int row = blockIdx.x;
    const int t = threadIdx.x;
    const float4* xr4 = (const float4*)(x + (size_t)row * DIM);
    float4 a = xr4[t];
    float4 b = xr4[t + 256];
    float s = (a.x + a.y) + (a.z + a.w) + (b.x + b.y) + (b.z + b.w);
    s = block_sum256(s, red);
    const float mu = s * (1.f / (float)DIM);
    float sq = 0.f;
    {
        float c;
        c = a.x - mu; sq += c * c;  c = a.y - mu; sq += c * c;
        c = a.z - mu; sq += c * c;  c = a.w - mu; sq += c * c;
        c = b.x - mu; sq += c * c;  c = b.y - mu; sq += c * c;
        c = b.z - mu; sq += c * c;  c = b.w - mu; sq += c * c;
    }
    sq = block_sum256(sq, red);
    const float rstd = rsqrtf(sq * (1.f / (float)DIM) + 1e-5f);
    const float4 g0 = ((const float4*)gamma)[t];
    const float4 g1 = ((const float4*)gamma)[t + 256];
    const float4 b0 = ((const float4*)beta)[t];
    const float4 b1 = ((const float4*)beta)[t + 256];
    float v[8];
    v[0] = (a.x - mu) * rstd * g0.x + b0.x;
    v[1] = (a.y - mu) * rstd * g0.y + b0.y;
    v[2] = (a.z - mu) * rstd * g0.z + b0.z;
    v[3] = (a.w - mu) * rstd * g0.w + b0.w;
    v[4] = (b.x - mu) * rstd * g1.x + b1.x;
    v[5] = (b.y - mu) * rstd * g1.y + b1.y;
    v[6] = (b.z - mu) * rstd * g1.z + b1.z;
    v[7] = (b.w - mu) * rstd * g1.w + b1.w;
    float mx = 0.f;
    #pragma unroll
    for (int j = 0; j < 8; j++) mx = fmaxf(mx, fabsf(v[j]));
    mx = block_max256(mx, red);
    const float xs = fmaxf(mx, 1e-6f);
    const float qs = 7.0f / xs;
    __half h[8];
    #pragma unroll
    for (int j = 0; j < 8; j++) {
        float r = rintf(v[j] * qs);          // round-half-even matches jnp.round
        r = fminf(fmaxf(r, -7.f), 7.f);
        h[j] = __float2half_rn(r);           // exact small integer
    }
    uint2* orow = (uint2*)(g_Xq + (size_t)row * DIM);
    uint2 p0, p1;
    p0.x = ((const uint32_t*)h)[0]; p0.y = ((const uint32_t*)h)[1];
    p1.x = ((const uint32_t*)h)[2]; p1.y = ((const uint32_t*)h)[3];
    orow[t]       = p0;
    orow[t + 256] = p1;
    if (t == 0) g_rowscale[row] = xs * (1.f / 7.f);
}

// ---------------------------------------------------------------------------
// K4: GEMM via mma.sync (HMMA fp16, fp32 accum), 2 CTAs/SM — R12-proven.
//   CTA 128x128, BK=64, 256 threads, 8 warps in 2x4 grid, warp tile 64x32.
//   3-stage cp.async ring; loads issued before compute each iter.
// ---------------------------------------------------------------------------
static __device__ __forceinline__ void load_A(uint32_t base, const __half* gA,
                                              int ksrc, int tid) {
    #pragma unroll
    for (int i = 0; i < 4; i++) {
        int idx = tid + i * GTHREADS;
        int r = idx >> 3, c = idx & 7;
        uint32_t so = (uint32_t)(r * 128 + ((c ^ (r & 7)) << 4));
        cp_async16(base + so, (const char*)(gA + (size_t)r * DIM + ksrc) + c * 16);
    }
}

static __device__ __forceinline__ void load_B(uint32_t base, const __half* gB,
                                              int ksrc, int tid) {
    #pragma unroll
    for (int i = 0; i < 4; i++) {
        int idx = tid + i * GTHREADS;
        int r = idx >> 3, c = idx & 7;
        uint32_t so = (uint32_t)(r * 128 + ((c ^ (r & 7)) << 4));
        cp_async16(base + so, (const char*)(gB + (size_t)r * DIM + ksrc) + c * 16);
    }
}

__global__ void __launch_bounds__(GTHREADS, 2)
k_gemm(float* __restrict__ out) {
    extern __shared__ char smem[];
    const uint32_t sb = smem_u32(smem);
    const int tid  = threadIdx.x;
    const int lane = tid & 31;
    const int wid  = tid >> 5;            // 0..7
    const int wm   = (wid >> 2) * 64;     // warp m-offset (2 rows of warps)
    const int wn   = (wid & 3) * 32;      // warp n-offset (4 cols of warps)

    // Supertile rasterization: 16 mt x 16 nt = 256-CTA supertiles.
    const int bid = blockIdx.x;           // 0..2047 (128 mt x 16 nt)
    const int st  = bid >> 8;             // 8 supertiles
    const int r8  = bid & 255;
    const int mt  = st * 16 + (r8 & 15);
    const int nt  = r8 >> 4;
    const int mBase = mt * BM;
    const int nBase = nt * BN;

    const __half* gA = g_Xq + (size_t)mBase * DIM;
    const __half* gB = g_Bq + (size_t)nBase * DIM;

    float acc[4][4][4];
    #pragma unroll
    for (int i = 0; i < 4; i++)
        #pragma unroll
        for (int j = 0; j < 4; j++)
            #pragma unroll
            for (int q = 0; q < 4; q++) acc[i][j][q] = 0.f;

    // Prologue: stages 0,1 <- kt 0,1
    #pragma unroll
    for (int p = 0; p < NSTAGE - 1; p++) {
        load_A(sb + p * STAGE, gA, p * BK, tid);
        load_B(sb + p * STAGE + ABYTES, gB, p * BK, tid);
        asm volatile("cp.async.commit_group;" ::: "memory");
    }

    int stage = 0;
    for (int kt = 0; kt < NKT; kt++) {
        if (kt < NKT - 1) asm volatile("cp.async.wait_group 1;" ::: "memory");
        else              asm volatile("cp.async.wait_group 0;" ::: "memory");
        __syncthreads();

        // Issue next-stage loads first: they overlap the MMA work below.
        if (kt + NSTAGE - 1 < NKT) {
            const int k2 = kt + NSTAGE - 1;
            int st2 = stage + NSTAGE - 1;
            if (st2 >= NSTAGE) st2 -= NSTAGE;
            const uint32_t nb = sb + st2 * STAGE;
            load_A(nb, gA, k2 * BK, tid);
            load_B(nb + ABYTES, gB, k2 * BK, tid);
            asm volatile("cp.async.commit_group;" ::: "memory");
        }

        const uint32_t aB = sb + stage * STAGE;
        const uint32_t bB = aB + ABYTES;

        #pragma unroll
        for (int ks = 0; ks < 4; ks++) {
            uint32_t af[4][4], bf[4][2];
            #pragma unroll
            for (int im = 0; im < 4; im++) {
                int r = wm + im * 16 + (lane & 15);
                uint32_t chunk = (uint32_t)((ks * 2 + (lane >> 4)) ^ (r & 7));
                ldmatrix_x4(af[im], aB + r * 128 + (chunk << 4));
            }
            #pragma unroll
            for (int in = 0; in < 4; in++) {
                int r = wn + in * 8 + (lane & 7);
                uint32_t chunk = (uint32_t)((ks * 2 + ((lane >> 3) & 1)) ^ (r & 7));
                ldmatrix_x2(bf[in], bB + r * 128 + (chunk << 4));
            }
            #pragma unroll
            for (int im = 0; im < 4; im++)
                #pragma unroll
                for (int in = 0; in < 4; in++)
                    mma_f16(acc[im][in], af[im], bf[in]);
        }

        stage = (stage + 1 == NSTAGE) ? 0 : stage + 1;
    }

    // Epilogue: d frag -> (row = lane/4 [+8], col = 2*(lane%4) [+1])
    #pragma unroll
    for (int im = 0; im < 4; im++) {
        const int r0 = mBase + wm + im * 16 + (lane >> 2);
        const int r1 = r0 + 8;
        const float s0 = g_rowscale[r0];
        const float s1 = g_rowscale[r1];
        #pragma unroll
        for (int in = 0; in < 4; in++) {
            const int col = nBase + wn + in * 8 + (lane & 3) * 2;
            float2 v0 = make_float2(acc[im][in][0] * s0, acc[im][in][1] * s0);
            float2 v1 = make_float2(acc[im][in][2] * s1, acc[im][in][3] * s1);
            *reinterpret_cast<float2*>(out + (size_t)r0 * DIM + col) = v0;
            *reinterpret_cast<float2*>(out + (size_t)r1 * DIM + col) = v1;
        }
    }
}

// ---------------------------------------------------------------------------
// Launcher
// ---------------------------------------------------------------------------
extern "C" void kernel_launch(void* const* d_in, const int* in_sizes, int n_in,
                              void* d_out, int out_size) {
    const float* x     = (const float*)d_in[0];
    const float* W     = (const float*)d_in[1];
    const float* gamma = (const float*)d_in[2];
    const float* beta  = (const float*)d_in[3];
    float* out = (float*)d_out;

    cudaFuncSetAttribute(k_gemm, cudaFuncAttributeMaxDynamicSharedMemorySize,
                         GEMM_SMEM);

    k_wabs_part<<<WPARTS, 256>>>(W);
    k_wabs_fin<<<1, 256>>>();
    k_wq_fwht<<<DIM, 256>>>(W);
    {
        dim3 tb(32, 8);
        dim3 tg(DIM / 32, DIM / 32);
        k_tr32<<<tg, tb>>>();
    }
    k_fwht_rows_half<<<DIM, 256>>>();
    {
        dim3 tb(32, 8);
        dim3 tg(DIM / 32, DIM / 32);
        k_tr16<<<tg, tb>>>();
    }
    k_ln_quant<<<NROWS, 256>>>(x, gamma, beta);

    k_gemm<<<(NROWS / BM) * (DIM / BN), GTHREADS, GEMM_SMEM>>>(out);
}